// round 5
// baseline (speedup 1.0000x reference)
#include <cuda_runtime.h>
#include <cuda_bf16.h>
#include <cstdint>

// Problem constants
#define MAXN 100000
#define IN_DIM 64
#define HID_DIM 128
#define OUT_DIM 64

// Scratch (device globals: allocation-free)
__device__ float g_Xt[(size_t)MAXN * IN_DIM];   // [N,64] transposed features
__device__ float g_Agg[(size_t)MAXN * IN_DIM];  // [N,64] aggregated features

typedef unsigned long long u64;

__device__ __forceinline__ u64 pack2(float lo, float hi) {
    u64 r;
    asm("mov.b64 %0, {%1, %2};" : "=l"(r) : "f"(lo), "f"(hi));
    return r;
}
__device__ __forceinline__ void unpack2(u64 v, float& lo, float& hi) {
    asm("mov.b64 {%0, %1}, %2;" : "=f"(lo), "=f"(hi) : "l"(v));
}
__device__ __forceinline__ u64 fma2(u64 a, u64 b, u64 c) {
    u64 d;
    asm("fma.rn.f32x2 %0, %1, %2, %3;" : "=l"(d) : "l"(a), "l"(b), "l"(c));
    return d;
}

// ---------------------------------------------------------------------------
// Zero the aggregation buffer (must be re-done every replay)
// ---------------------------------------------------------------------------
__global__ void zero_kernel(int n_float4) {
    int i = blockIdx.x * blockDim.x + threadIdx.x;
    if (i < n_float4) {
        ((float4*)g_Agg)[i] = make_float4(0.f, 0.f, 0.f, 0.f);
    }
}

// ---------------------------------------------------------------------------
// Transpose inp [64, N] -> g_Xt [N, 64]
// ---------------------------------------------------------------------------
__global__ void transpose_kernel(const float* __restrict__ inp, int N) {
    __shared__ float tile[32][33];
    int n0 = blockIdx.x * 32;
    int d0 = blockIdx.y * 32;   // 0 or 32
    int tx = threadIdx.x, ty = threadIdx.y;
    #pragma unroll
    for (int r = ty; r < 32; r += 8) {
        int n = n0 + tx;
        tile[r][tx] = (n < N) ? inp[(size_t)(d0 + r) * N + n] : 0.f;
    }
    __syncthreads();
    #pragma unroll
    for (int r = ty; r < 32; r += 8) {
        int n = n0 + r;
        if (n < N) g_Xt[(size_t)n * 64 + d0 + tx] = tile[tx][r];
    }
}

// ---------------------------------------------------------------------------
// Scatter-add: g_Agg[dst] += g_Xt[src]. 16 threads per edge, one red.v4 each.
// ---------------------------------------------------------------------------
__global__ void scatter_kernel(const int* __restrict__ src,
                               const int* __restrict__ dst, int E) {
    int t = blockIdx.x * blockDim.x + threadIdx.x;
    int e = t >> 4;
    int j = t & 15;
    if (e < E) {
        int s = src[e];
        int d = dst[e];
        const float4* xs = (const float4*)g_Xt;
        float4 v = xs[(size_t)s * 16 + j];
        float4* ag = (float4*)g_Agg;
        float4* p = &ag[(size_t)d * 16 + j];
        asm volatile("red.global.add.v4.f32 [%0], {%1, %2, %3, %4};"
                     :: "l"(p), "f"(v.x), "f"(v.y), "f"(v.z), "f"(v.w)
                     : "memory");
    }
}

// ---------------------------------------------------------------------------
// Fused MLP: out[o, n] = (relu(agg[n] @ W1^T + b1) @ W2^T + b2)[o]
// Weights pre-paired in smem so packed f32x2 FMAs take u64 operands directly.
//   W1p[k*64 + j2]  = {W1[2j2, k],  W1[2j2+1, k]}   (64 k x 64 j2 float2)
//   W2p[h*32 + o2]  = {W2[2o2, h],  W2[2o2+1, h]}   (128 h x 32 o2 float2)
// One thread per node: 8192 fma.f32x2 = 16384 FMA ops.
// ---------------------------------------------------------------------------
#define MLP_SMEM_BYTES (64 * 64 * 8 + 128 * 32 * 8 + 128 * 4 + 64 * 4)

__global__ __launch_bounds__(256, 1)
void mlp_kernel(const float* __restrict__ W1, const float* __restrict__ b1,
                const float* __restrict__ W2, const float* __restrict__ b2,
                float* __restrict__ out, int N) {
    extern __shared__ float smem[];
    float2* W1p = (float2*)smem;                       // 4096 float2 (32KB)
    float2* W2p = (float2*)(smem + 8192);              // 4096 float2 (32KB)
    float*  b1s = smem + 16384;                        // 128
    float*  b2s = smem + 16384 + 128;                  // 64
    const u64* W1q = (const u64*)W1p;
    const u64* W2q = (const u64*)W2p;

    int tid = threadIdx.x;

    // Build paired weight layouts cooperatively
    for (int i = tid; i < 64 * 64; i += 256) {         // i = k*64 + j2
        int k = i >> 6, j2 = i & 63;
        W1p[i] = make_float2(W1[(2 * j2) * 64 + k], W1[(2 * j2 + 1) * 64 + k]);
    }
    for (int i = tid; i < 128 * 32; i += 256) {        // i = h*32 + o2
        int h = i >> 5, o2 = i & 31;
        W2p[i] = make_float2(W2[(2 * o2) * 128 + h], W2[(2 * o2 + 1) * 128 + h]);
    }
    if (tid < 128) b1s[tid] = b1[tid];
    if (tid < 64)  b2s[tid] = b2[tid];
    __syncthreads();

    int n = blockIdx.x * 256 + tid;
    if (n >= N) return;

    // Load this node's aggregated features (16 x LDG.128)
    float x[64];
    const float4* xg = (const float4*)(g_Agg + (size_t)n * 64);
    #pragma unroll
    for (int i = 0; i < 16; i++) {
        float4 v = xg[i];
        x[4 * i + 0] = v.x; x[4 * i + 1] = v.y;
        x[4 * i + 2] = v.z; x[4 * i + 3] = v.w;
    }

    // Output accumulators: 32 packed pairs = 64 outputs
    u64 acc[32];
    #pragma unroll
    for (int o2 = 0; o2 < 32; o2++)
        acc[o2] = pack2(b2s[2 * o2], b2s[2 * o2 + 1]);

    // 8 chunks of 16 hidden units (8 packed pairs each)
    #pragma unroll
    for (int c = 0; c < 8; c++) {
        u64 a2[8];
        #pragma unroll
        for (int jj = 0; jj < 8; jj++)
            a2[jj] = pack2(b1s[c * 16 + 2 * jj], b1s[c * 16 + 2 * jj + 1]);

        #pragma unroll
        for (int k = 0; k < 64; k++) {
            u64 xx = pack2(x[k], x[k]);
            #pragma unroll
            for (int jj = 0; jj < 8; jj += 2) {
                ulonglong2 w = *(const ulonglong2*)&W1q[k * 64 + c * 8 + jj];
                a2[jj]     = fma2(w.x, xx, a2[jj]);
                a2[jj + 1] = fma2(w.y, xx, a2[jj + 1]);
            }
        }

        float h[16];
        #pragma unroll
        for (int jj = 0; jj < 8; jj++) {
            float lo, hi;
            unpack2(a2[jj], lo, hi);
            h[2 * jj]     = fmaxf(lo, 0.f);
            h[2 * jj + 1] = fmaxf(hi, 0.f);
        }

        #pragma unroll
        for (int jj = 0; jj < 16; jj++) {
            u64 hh = pack2(h[jj], h[jj]);
            int hidx = c * 16 + jj;
            #pragma unroll
            for (int o2 = 0; o2 < 32; o2 += 2) {
                ulonglong2 w = *(const ulonglong2*)&W2q[hidx * 32 + o2];
                acc[o2]     = fma2(w.x, hh, acc[o2]);
                acc[o2 + 1] = fma2(w.y, hh, acc[o2 + 1]);
            }
        }
    }

    // Store: out is [64, N]
    #pragma unroll
    for (int o2 = 0; o2 < 32; o2++) {
        float lo, hi;
        unpack2(acc[o2], lo, hi);
        out[(size_t)(2 * o2) * N + n]     = lo;
        out[(size_t)(2 * o2 + 1) * N + n] = hi;
    }
}

// ---------------------------------------------------------------------------
extern "C" void kernel_launch(void* const* d_in, const int* in_sizes, int n_in,
                              void* d_out, int out_size) {
    const float* inp = (const float*)d_in[0];   // [64, N]
    const int*   src = (const int*)d_in[1];     // [E]
    const int*   dst = (const int*)d_in[2];     // [E]
    const float* W1  = (const float*)d_in[3];   // [128, 64]
    const float* b1  = (const float*)d_in[4];   // [128]
    const float* W2  = (const float*)d_in[5];   // [64, 128]
    const float* b2  = (const float*)d_in[6];   // [64]
    float* out = (float*)d_out;                 // [64, N]

    int N = in_sizes[0] / IN_DIM;
    int E = in_sizes[1];

    cudaFuncSetAttribute(mlp_kernel,
                         cudaFuncAttributeMaxDynamicSharedMemorySize,
                         MLP_SMEM_BYTES);

    int n_f4 = N * 16;
    zero_kernel<<<(n_f4 + 255) / 256, 256>>>(n_f4);
    transpose_kernel<<<dim3((N + 31) / 32, 2), dim3(32, 8)>>>(inp, N);
    long long st = (long long)E * 16;
    scatter_kernel<<<(unsigned)((st + 255) / 256), 256>>>(src, dst, E);
    mlp_kernel<<<(N + 255) / 256, 256, MLP_SMEM_BYTES>>>(W1, b1, W2, b2, out, N);
}

// round 9
// speedup vs baseline: 1.1437x; 1.1437x over previous
#include <cuda_runtime.h>
#include <cuda_bf16.h>
#include <cstdint>

// Problem constants
#define MAXN 100000
#define IN_DIM 64
#define HID_DIM 128
#define OUT_DIM 64

// Scratch (device globals: allocation-free)
__device__ float g_Xt[(size_t)MAXN * IN_DIM];   // [N,64] transposed features
__device__ float g_Agg[(size_t)MAXN * IN_DIM];  // [N,64] aggregated features

typedef unsigned long long u64;

__device__ __forceinline__ u64 pack2(float lo, float hi) {
    u64 r;
    asm("mov.b64 %0, {%1, %2};" : "=l"(r) : "f"(lo), "f"(hi));
    return r;
}
__device__ __forceinline__ void unpack2(u64 v, float& lo, float& hi) {
    asm("mov.b64 {%0, %1}, %2;" : "=f"(lo), "=f"(hi) : "l"(v));
}
__device__ __forceinline__ u64 fma2(u64 a, u64 b, u64 c) {
    u64 d;
    asm("fma.rn.f32x2 %0, %1, %2, %3;" : "=l"(d) : "l"(a), "l"(b), "l"(c));
    return d;
}
__device__ __forceinline__ u64 add2(u64 a, u64 b) {
    u64 d;
    asm("add.rn.f32x2 %0, %1, %2;" : "=l"(d) : "l"(a), "l"(b));
    return d;
}

// ---------------------------------------------------------------------------
// Zero the aggregation buffer (must be re-done every replay)
// ---------------------------------------------------------------------------
__global__ void zero_kernel(int n_float4) {
    int i = blockIdx.x * blockDim.x + threadIdx.x;
    if (i < n_float4) {
        ((float4*)g_Agg)[i] = make_float4(0.f, 0.f, 0.f, 0.f);
    }
}

// ---------------------------------------------------------------------------
// Transpose inp [64, N] -> g_Xt [N, 64]
// ---------------------------------------------------------------------------
__global__ void transpose_kernel(const float* __restrict__ inp, int N) {
    __shared__ float tile[32][33];
    int n0 = blockIdx.x * 32;
    int d0 = blockIdx.y * 32;   // 0 or 32
    int tx = threadIdx.x, ty = threadIdx.y;
    #pragma unroll
    for (int r = ty; r < 32; r += 8) {
        int n = n0 + tx;
        tile[r][tx] = (n < N) ? inp[(size_t)(d0 + r) * N + n] : 0.f;
    }
    __syncthreads();
    #pragma unroll
    for (int r = ty; r < 32; r += 8) {
        int n = n0 + r;
        if (n < N) g_Xt[(size_t)n * 64 + d0 + tx] = tile[tx][r];
    }
}

// ---------------------------------------------------------------------------
// Scatter-add: g_Agg[dst] += g_Xt[src]. 16 threads per edge, one red.v4 each.
// ---------------------------------------------------------------------------
__global__ void scatter_kernel(const int* __restrict__ src,
                               const int* __restrict__ dst, int E) {
    int t = blockIdx.x * blockDim.x + threadIdx.x;
    int e = t >> 4;
    int j = t & 15;
    if (e < E) {
        int s = src[e];
        int d = dst[e];
        const float4* xs = (const float4*)g_Xt;
        float4 v = xs[(size_t)s * 16 + j];
        float4* ag = (float4*)g_Agg;
        float4* p = &ag[(size_t)d * 16 + j];
        asm volatile("red.global.add.v4.f32 [%0], {%1, %2, %3, %4};"
                     :: "l"(p), "f"(v.x), "f"(v.y), "f"(v.z), "f"(v.w)
                     : "memory");
    }
}

// ---------------------------------------------------------------------------
// Fused MLP, lane-pair split: 2 threads per node (lane, lane^1).
//   half hf=0: input features k in [0,32),  outputs o in [0,32)
//   half hf=1: input features k in [32,64), outputs o in [32,64)
// Hidden partials combined via shfl.xor(1) + add.rn.f32x2 (both lanes end up
// with the full hidden chunk).
//
// Paired smem weight layouts (u64 = {even_row, odd_row}):
//   W1q[hf*2052 + kk*64 + j2], kk = k - hf*32   (32B pad between halves
//   W2q[hf*2052 + hid*16 + o2l], o2l local pair   -> disjoint LDS banks)
// ---------------------------------------------------------------------------
#define HALF_STRIDE 2052                        // 2048 u64 + 4 u64 pad
#define MLP_SMEM_BYTES (2 * HALF_STRIDE * 2 * 8 + 128 * 4 + 64 * 4)

__global__ __launch_bounds__(512, 1)
void mlp_kernel(const float* __restrict__ W1, const float* __restrict__ b1,
                const float* __restrict__ W2, const float* __restrict__ b2,
                float* __restrict__ out, int N) {
    extern __shared__ float smem[];
    u64* W1q = (u64*)smem;                          // 2*2052 u64
    u64* W2q = W1q + 2 * HALF_STRIDE;               // 2*2052 u64
    float* b1s = (float*)(W2q + 2 * HALF_STRIDE);   // 128
    float* b2s = b1s + 128;                         // 64

    int tid = threadIdx.x;

    // Build paired weight layouts cooperatively
    for (int i = tid; i < 64 * 64; i += 512) {      // i = k*64 + j2
        int k = i >> 6, j2 = i & 63;
        int hf = k >> 5, kk = k & 31;
        W1q[hf * HALF_STRIDE + kk * 64 + j2] =
            pack2(W1[(2 * j2) * 64 + k], W1[(2 * j2 + 1) * 64 + k]);
    }
    for (int i = tid; i < 128 * 32; i += 512) {     // i = hid*32 + o2
        int hid = i >> 5, o2 = i & 31;
        int hf = o2 >> 4, o2l = o2 & 15;
        W2q[hf * HALF_STRIDE + hid * 16 + o2l] =
            pack2(W2[(2 * o2) * 128 + hid], W2[(2 * o2 + 1) * 128 + hid]);
    }
    if (tid < 128) b1s[tid] = b1[tid];
    if (tid < 64)  b2s[tid] = b2[tid];
    __syncthreads();

    int pairid = tid >> 1;
    int hf = tid & 1;
    int n_raw = blockIdx.x * 256 + pairid;
    bool valid = (n_raw < N);
    int n = valid ? n_raw : (N - 1);   // clamp: all lanes stay active for shfl

    const u64* w1t = W1q + hf * HALF_STRIDE;
    const u64* w2t = W2q + hf * HALF_STRIDE;

    // This thread's half of the node features (8 x LDG.128)
    float x[32];
    const float4* xg = (const float4*)(g_Agg + (size_t)n * 64 + hf * 32);
    #pragma unroll
    for (int i = 0; i < 8; i++) {
        float4 v = xg[i];
        x[4 * i + 0] = v.x; x[4 * i + 1] = v.y;
        x[4 * i + 2] = v.z; x[4 * i + 3] = v.w;
    }

    // Output accumulators: 16 packed pairs = this half's 32 outputs
    u64 acc[16];
    #pragma unroll
    for (int o2 = 0; o2 < 16; o2++)
        acc[o2] = pack2(b2s[hf * 32 + 2 * o2], b2s[hf * 32 + 2 * o2 + 1]);

    // 8 chunks of 16 hidden units (8 packed pairs each)
    #pragma unroll
    for (int c = 0; c < 8; c++) {
        u64 a2[8];
        #pragma unroll
        for (int jj = 0; jj < 8; jj++)
            a2[jj] = hf ? 0ULL
                        : pack2(b1s[c * 16 + 2 * jj], b1s[c * 16 + 2 * jj + 1]);

        #pragma unroll
        for (int kk = 0; kk < 32; kk++) {
            u64 xx = pack2(x[kk], x[kk]);
            #pragma unroll
            for (int jj = 0; jj < 8; jj += 2) {
                ulonglong2 w = *(const ulonglong2*)&w1t[kk * 64 + c * 8 + jj];
                a2[jj]     = fma2(w.x, xx, a2[jj]);
                a2[jj + 1] = fma2(w.y, xx, a2[jj + 1]);
            }
        }

        // Combine lane-pair partial sums: both lanes get the full chunk
        float hv[16];
        #pragma unroll
        for (int jj = 0; jj < 8; jj++) {
            u64 other = __shfl_xor_sync(0xffffffffu, a2[jj], 1);
            u64 full  = add2(a2[jj], other);
            float lo, hi;
            unpack2(full, lo, hi);
            hv[2 * jj]     = fmaxf(lo, 0.f);
            hv[2 * jj + 1] = fmaxf(hi, 0.f);
        }

        #pragma unroll
        for (int jj = 0; jj < 16; jj++) {
            u64 hh = pack2(hv[jj], hv[jj]);
            int hidx = c * 16 + jj;
            #pragma unroll
            for (int o2 = 0; o2 < 16; o2 += 2) {
                ulonglong2 w = *(const ulonglong2*)&w2t[hidx * 16 + o2];
                acc[o2]     = fma2(w.x, hh, acc[o2]);
                acc[o2 + 1] = fma2(w.y, hh, acc[o2 + 1]);
            }
        }
    }

    // Store this half's 32 outputs: out is [64, N]
    if (valid) {
        #pragma unroll
        for (int o2 = 0; o2 < 16; o2++) {
            float lo, hi;
            unpack2(acc[o2], lo, hi);
            out[(size_t)(hf * 32 + 2 * o2) * N + n]     = lo;
            out[(size_t)(hf * 32 + 2 * o2 + 1) * N + n] = hi;
        }
    }
}

// ---------------------------------------------------------------------------
extern "C" void kernel_launch(void* const* d_in, const int* in_sizes, int n_in,
                              void* d_out, int out_size) {
    const float* inp = (const float*)d_in[0];   // [64, N]
    const int*   src = (const int*)d_in[1];     // [E]
    const int*   dst = (const int*)d_in[2];     // [E]
    const float* W1  = (const float*)d_in[3];   // [128, 64]
    const float* b1  = (const float*)d_in[4];   // [128]
    const float* W2  = (const float*)d_in[5];   // [64, 128]
    const float* b2  = (const float*)d_in[6];   // [64]
    float* out = (float*)d_out;                 // [64, N]

    int N = in_sizes[0] / IN_DIM;
    int E = in_sizes[1];

    cudaFuncSetAttribute(mlp_kernel,
                         cudaFuncAttributeMaxDynamicSharedMemorySize,
                         MLP_SMEM_BYTES);

    int n_f4 = N * 16;
    zero_kernel<<<(n_f4 + 255) / 256, 256>>>(n_f4);
    transpose_kernel<<<dim3((N + 31) / 32, 2), dim3(32, 8)>>>(inp, N);
    long long st = (long long)E * 16;
    scatter_kernel<<<(unsigned)((st + 255) / 256), 256>>>(src, dst, E);
    // 512 threads = 256 nodes per CTA (2 threads/node)
    mlp_kernel<<<(N + 255) / 256, 512, MLP_SMEM_BYTES>>>(W1, b1, W2, b2, out, N);
}